// round 3
// baseline (speedup 1.0000x reference)
#include <cuda_runtime.h>
#include <cstdint>

// adj: (B=2, N=2048, N=2048, F=16) fp32
// f=8, stride=4 -> starts S=511; off-diagonal offsets NOFF=56
// out: (B, S, 56*16) fp32 = 915712 floats
//
// One thread per (b, s, off): copies 16 contiguous floats (4x float4).
// local = off + 1 + off/8; ii = local/8; jj = local%8
// row = 4*s + ii, col = 4*s + jj
// src base float4 idx = (((b*N + row)*N + col) * 4)
// dst base float4 idx = tid * 4   (out layout matches linear tid -> coalesced)

namespace {
constexpr int B = 2;
constexpr int N = 2048;
constexpr int STRIDE = 4;
constexpr int S = 511;
constexpr int NOFF = 56;
constexpr int TOTAL = B * S * NOFF;   // 57232 threads
}

__global__ void __launch_bounds__(256)
sparse_diag_unfold_kernel(const float4* __restrict__ adj,
                          float4* __restrict__ out) {
    int tid = blockIdx.x * blockDim.x + threadIdx.x;
    if (tid >= TOTAL) return;

    // tid = (b*S + s)*NOFF + off
    int off = tid % NOFF;
    int bs  = tid / NOFF;
    int s   = bs % S;
    int b   = bs / S;

    int local = off + 1 + (off >> 3);
    int ii = local >> 3;
    int jj = local & 7;

    int row = s * STRIDE + ii;
    int col = s * STRIDE + jj;

    // float4 index into adj (16 floats = 4 float4 per element row)
    long long src = (((long long)b * N + row) * N + col) * 4;
    long long dst = (long long)tid * 4;

    float4 v0 = adj[src + 0];
    float4 v1 = adj[src + 1];
    float4 v2 = adj[src + 2];
    float4 v3 = adj[src + 3];

    out[dst + 0] = v0;
    out[dst + 1] = v1;
    out[dst + 2] = v2;
    out[dst + 3] = v3;
}

extern "C" void kernel_launch(void* const* d_in, const int* in_sizes, int n_in,
                              void* d_out, int out_size) {
    const float4* adj = (const float4*)d_in[0];
    float4* out = (float4*)d_out;

    const int threads = 256;
    const int blocks = (TOTAL + threads - 1) / threads;   // 224
    sparse_diag_unfold_kernel<<<blocks, threads>>>(adj, out);
}

// round 4
// speedup vs baseline: 1.0047x; 1.0047x over previous
#include <cuda_runtime.h>
#include <cstdint>

// adj: (B=2, N=2048, N=2048, F=16) fp32
// f=8, stride=4 -> S=511 window starts; NOFF=56 off-diagonal offsets
// out: (B, S, 56*16) fp32 = 915712 floats = 228928 float4
//
// One thread per HALF-element (2x float4 = 8 floats). MLP=2 per thread,
// 114464 threads -> 448 blocks of 256 -> ~24 warps/SM (vs 12 in R3, vs
// MLP=1 in R2). Output float4 index = tid*2 (+0,+1): fully coalesced.

namespace {
constexpr int B = 2;
constexpr int N = 2048;
constexpr int STRIDE = 4;
constexpr int S = 511;
constexpr int NOFF = 56;
constexpr int TOTAL_PAIRS = B * S * NOFF * 2;   // 114464
}

__global__ void __launch_bounds__(256)
sparse_diag_unfold_kernel(const float4* __restrict__ adj,
                          float4* __restrict__ out) {
    int tid = blockIdx.x * blockDim.x + threadIdx.x;
    if (tid >= TOTAL_PAIRS) return;

    int half = tid & 1;          // which 8-float half of the 16-float element
    int e    = tid >> 1;         // element index: (b*S + s)*NOFF + off
    int off  = e % NOFF;
    int bs   = e / NOFF;
    int s    = bs % S;
    int b    = bs / S;

    int local = off + 1 + (off >> 3);   // skip diagonal (local % 9 == 0)
    int ii = local >> 3;
    int jj = local & 7;

    int row = s * STRIDE + ii;
    int col = s * STRIDE + jj;

    // float4 index into adj: element base has 4 float4; this thread takes 2.
    long long src = ((((long long)b * N + row) * N + col) << 2) + (half << 1);
    long long dst = (long long)tid << 1;

    float4 v0 = adj[src + 0];
    float4 v1 = adj[src + 1];

    out[dst + 0] = v0;
    out[dst + 1] = v1;
}

extern "C" void kernel_launch(void* const* d_in, const int* in_sizes, int n_in,
                              void* d_out, int out_size) {
    const float4* adj = (const float4*)d_in[0];
    float4* out = (float4*)d_out;

    const int threads = 256;
    const int blocks = (TOTAL_PAIRS + threads - 1) / threads;   // 448
    sparse_diag_unfold_kernel<<<blocks, threads>>>(adj, out);
}